// round 12
// baseline (speedup 1.0000x reference)
#include <cuda_runtime.h>
#include <stdint.h>

#define BB 16
#define NN 2048
#define KK 20
#define ROWS (BB * NN)
#define LSTRIDE 512          // adjacency entries per row (20 direct + transpose)
#define TCAP (LSTRIDE - KK)
#define CAP 256              // smem candidate capacity
#define TH1 2.2f
#define PREF1 2.19978f       // 2.2 - 1.1e-4 (margin covers rounding; noise < 1)
#define TH2 1.8f
#define PREF2 1.79978f

// ---- scratch (static __device__ — no allocations allowed) ----
__device__ unsigned long long g_list[(size_t)ROWS * LSTRIDE]; // (col<<32)|bits(v)
__device__ int   g_tcnt[ROWS];   // transpose counters (zero-init; writer re-zeroes)
__device__ float g_dinv[ROWS];

__device__ __forceinline__ unsigned long long u64max(unsigned long long a,
                                                     unsigned long long b) {
    return a > b ? a : b;
}

// emit winner (col, relu value v) of `row` into slot s of the adjacency lists
__device__ __forceinline__ void emit(int row, int b, int s, int col, float v) {
    g_list[(size_t)row * LSTRIDE + s] =
        ((unsigned long long)col << 32) | (unsigned long long)__float_as_uint(v);
    int jrow = b * NN + col;
    uint32_t t = atomicAdd((unsigned int*)&g_tcnt[jrow], 1u);
    if (t < TCAP)
        g_list[(size_t)jrow * LSTRIDE + KK + t] =
            ((unsigned long long)(row & 2047) << 32)
          | (unsigned long long)__float_as_uint(v);
}

// ---------------------------------------------------------------------------
// One block (256 threads) per row. Streams ONLY A (coalesced float4).
// Register pre-filter a > TH-1.1e-4 collects a superset of {doped > TH};
// a short scattered phase loads noise for just those ~29 candidates, builds
// exact doped keys, and certifies (#{doped>TH} >= K  =>  global top-K lies in
// the candidate set). Exact rank-count with jax's lowest-index tie-break
// (key = doped_bits<<11 | (2047-col)); slot = rank. Ladder: 2.2 -> 1.8 ->
// register-resident 20-pass block-max over all 2048 (exact safety net).
__global__ __launch_bounds__(256) void k_topk(const float* __restrict__ A,
                                              const float* __restrict__ Noise) {
    const int row  = blockIdx.x;       // b * NN + i
    const int tid  = threadIdx.x;
    const int b    = row >> 11;
    const size_t base = (size_t)row << 11;

    __shared__ unsigned long long sP[CAP];   // (a_bits << 11) | col
    __shared__ unsigned long long sK[CAP];   // (doped_bits << 11) | (2047-col)
    __shared__ float    sV[CAP];             // relu value (= a, since a > 1.8)
    __shared__ uint32_t s_cnt, s_cert;
    __shared__ unsigned long long s_red[8], s_win;

    const float4* a4 = (const float4*)(A + base);
    float4 av  = __ldcs(a4 + tid);
    float4 av2 = __ldcs(a4 + 256 + tid);
    float aa[8] = {av.x, av.y, av.z, av.w, av2.x, av2.y, av2.z, av2.w};

    if (tid == 0) s_cnt = 0;
    __syncthreads();

    // ---- tier 1 pre-filter @ (2.2 - margin), registers only ----
#pragma unroll
    for (int e = 0; e < 8; e++) {
        if (aa[e] > PREF1) {
            int col = (e < 4) ? (tid * 4 + e) : (1024 + tid * 4 + (e - 4));
            uint32_t p = atomicAdd(&s_cnt, 1u);
            if (p < CAP)
                sP[p] = ((unsigned long long)__float_as_uint(aa[e]) << 11)
                      | (unsigned long long)col;
        }
    }
    __syncthreads();
    uint32_t M = s_cnt;
    bool ok = false;

    if (M >= KK && M <= CAP) {
        // ---- phase 2: scattered noise for candidates, certify @2.2 ----
        if (tid == 0) s_cert = 0;
        __syncthreads();
        const uint32_t THB = __float_as_uint(TH1);
        for (uint32_t i = tid; i < M; i += 256) {
            unsigned long long e = sP[i];
            int   col = (int)(e & 2047u);
            float a   = __uint_as_float((uint32_t)(e >> 11));
            float n   = __ldg(Noise + base + col);
            float d   = __fadd_rn(a, __fmul_rn(n, 1e-4f));
            uint32_t dbits = __float_as_uint(d);
            sK[i] = ((unsigned long long)dbits << 11)
                  | (unsigned long long)(2047 - col);
            sV[i] = a;
            if (dbits > THB) atomicAdd(&s_cert, 1u);
        }
        __syncthreads();
        ok = (s_cert >= KK);
    }

    if (!ok) {
        // ---- tier 2: re-filter @ (1.8 - margin) from registers ----
        __syncthreads();
        if (tid == 0) s_cnt = 0;
        __syncthreads();
#pragma unroll
        for (int e = 0; e < 8; e++) {
            if (aa[e] > PREF2) {
                int col = (e < 4) ? (tid * 4 + e) : (1024 + tid * 4 + (e - 4));
                uint32_t p = atomicAdd(&s_cnt, 1u);
                if (p < CAP)
                    sP[p] = ((unsigned long long)__float_as_uint(aa[e]) << 11)
                          | (unsigned long long)col;
            }
        }
        __syncthreads();
        M = s_cnt;
        if (M >= KK && M <= CAP) {
            if (tid == 0) s_cert = 0;
            __syncthreads();
            const uint32_t THB = __float_as_uint(TH2);
            for (uint32_t i = tid; i < M; i += 256) {
                unsigned long long e = sP[i];
                int   col = (int)(e & 2047u);
                float a   = __uint_as_float((uint32_t)(e >> 11));
                float n   = __ldg(Noise + base + col);
                float d   = __fadd_rn(a, __fmul_rn(n, 1e-4f));
                uint32_t dbits = __float_as_uint(d);
                sK[i] = ((unsigned long long)dbits << 11)
                      | (unsigned long long)(2047 - col);
                sV[i] = a;
                if (dbits > THB) atomicAdd(&s_cert, 1u);
            }
            __syncthreads();
            ok = (s_cert >= KK);
        }
    }

    if (ok) {
        // ---- exact rank-count within certified superset; slot = rank ----
        for (uint32_t i = tid; i < M; i += 256) {
            const unsigned long long key = sK[i];
            uint32_t rank = 0;
#pragma unroll 4
            for (uint32_t q = 0; q < M; q++)
                rank += (sK[q] > key);
            if (rank < KK)
                emit(row, b, (int)rank, 2047 - (int)(key & 2047u), sV[i]);
        }
        return;
    }

    // ---- tier 3 (P ~ 1e-9/row): exact 20-pass block-max over all keys ----
    {
        const float4* n4 = (const float4*)(Noise + base);
        float4 nv  = __ldg(n4 + tid);
        float4 nv2 = __ldg(n4 + 256 + tid);
        float no[8] = {nv.x, nv.y, nv.z, nv.w, nv2.x, nv2.y, nv2.z, nv2.w};
        uint32_t alive = 0xFFu;
        for (int pass = 0; pass < KK; pass++) {
            unsigned long long m = 0;
#pragma unroll
            for (int e = 0; e < 8; e++) {
                if (alive & (1u << e)) {
                    int col = (e < 4) ? (tid * 4 + e) : (1024 + tid * 4 + (e - 4));
                    float r = fmaxf(aa[e], 0.0f);
                    float d = __fadd_rn(r, __fmul_rn(no[e], 1e-4f));
                    unsigned long long k =
                        ((unsigned long long)__float_as_uint(d) << 11)
                      | (unsigned long long)(2047 - col);
                    m = u64max(m, k);
                }
            }
#pragma unroll
            for (int off = 16; off; off >>= 1)
                m = u64max(m, __shfl_down_sync(0xffffffffu, m, off));
            if ((tid & 31) == 0) s_red[tid >> 5] = m;
            __syncthreads();
            if (tid == 0) {
                unsigned long long w = s_red[0];
#pragma unroll
                for (int j = 1; j < 8; j++) w = u64max(w, s_red[j]);
                s_win = w;
            }
            __syncthreads();
            unsigned long long w = s_win;
#pragma unroll
            for (int e = 0; e < 8; e++) {
                if (alive & (1u << e)) {
                    int col = (e < 4) ? (tid * 4 + e) : (1024 + tid * 4 + (e - 4));
                    float r = fmaxf(aa[e], 0.0f);
                    float d = __fadd_rn(r, __fmul_rn(no[e], 1e-4f));
                    unsigned long long k =
                        ((unsigned long long)__float_as_uint(d) << 11)
                      | (unsigned long long)(2047 - col);
                    if (k == w) {
                        emit(row, b, pass, col, r);
                        alive &= ~(1u << e);
                    }
                }
            }
            __syncthreads();
        }
    }
}

// ---------------------------------------------------------------------------
// Warp per row: d_i = 1 + 0.5 * sum(list values); dinv = rsqrt(d_i).
__global__ __launch_bounds__(256) void k_deg() {
    int warp = (blockIdx.x * 256 + threadIdx.x) >> 5;
    int lane = threadIdx.x & 31;
    if (warp >= ROWS) return;
    int tc = g_tcnt[warp]; if (tc > TCAP) tc = TCAP;
    int n  = KK + tc;
    float s = 0.0f;
    const unsigned long long* lst = g_list + (size_t)warp * LSTRIDE;
    for (int i = lane; i < n; i += 32)
        s += __uint_as_float((uint32_t)lst[i]);
#pragma unroll
    for (int off = 16; off; off >>= 1)
        s += __shfl_down_sync(0xffffffffu, s, off);
    if (lane == 0)
        g_dinv[warp] = rsqrtf(fmaf(0.5f, s, 1.0f));
}

// ---------------------------------------------------------------------------
// Block per row: zero smem row, scatter weighted entries + diagonal (dinv via
// L2-hot __ldg), stream dense row out evict-first; re-zero counter.
__global__ __launch_bounds__(256) void k_writer(float* __restrict__ out) {
    const int row = blockIdx.x;
    const int tid = threadIdx.x;
    const int b   = row >> 11;

    __shared__ float srow[NN];
    float4* s4 = (float4*)srow;
    s4[tid]       = make_float4(0.f, 0.f, 0.f, 0.f);
    s4[256 + tid] = make_float4(0.f, 0.f, 0.f, 0.f);

    const float di = g_dinv[row];
    int tc = g_tcnt[row]; if (tc > TCAP) tc = TCAP;
    const int n = KK + tc;
    __syncthreads();

    const unsigned long long* lst = g_list + (size_t)row * LSTRIDE;
    for (int t = tid; t < n; t += 256) {
        unsigned long long e = lst[t];
        int   col = (int)(e >> 32);
        float v   = __uint_as_float((uint32_t)e);
        float w   = 0.5f * v * di * __ldg(&g_dinv[b * NN + col]);
        atomicAdd(&srow[col], w);
    }
    if (tid == 0) atomicAdd(&srow[row & 2047], di * di);
    __syncthreads();

    float4* o4 = (float4*)(out + ((size_t)row << 11));
    __stcs(&o4[tid],       s4[tid]);
    __stcs(&o4[256 + tid], s4[256 + tid]);

    if (tid == 0) g_tcnt[row] = 0;   // next call sees zeroed counters
}

// ---------------------------------------------------------------------------
extern "C" void kernel_launch(void* const* d_in, const int* in_sizes, int n_in,
                              void* d_out, int out_size) {
    const float* A     = (const float*)d_in[0];
    const float* Noise = (const float*)d_in[1];
    float* out = (float*)d_out;

    k_topk  <<<ROWS, 256>>>(A, Noise);
    k_deg   <<<(ROWS * 32 + 255) / 256, 256>>>();
    k_writer<<<ROWS, 256>>>(out);
}

// round 13
// speedup vs baseline: 1.6060x; 1.6060x over previous
#include <cuda_runtime.h>
#include <stdint.h>

#define BB 16
#define NN 2048
#define KK 20
#define ROWS (BB * NN)
#define LSTRIDE 512          // adjacency entries per row (20 direct + transpose)
#define TCAP (LSTRIDE - KK)
#define CAP 256              // smem candidate capacity in the fast kernel
#define TH1 2.2f
#define PREF1 2.19978f       // 2.2 - 1.1e-4 (covers rounding; noise in [0,1))
#define TH2 1.8f

// ---- scratch (static __device__ — no allocations allowed) ----
__device__ unsigned long long g_list[(size_t)ROWS * LSTRIDE]; // (col<<32)|bits(v)
__device__ int g_tcnt[ROWS];    // transpose counters (zero-init; writer re-zeroes)
__device__ float g_dinv[ROWS];
__device__ int g_retry[ROWS];   // rows needing the slow exact path
__device__ int g_retry_cnt;     // zero-init; writer re-zeroes

// emit winner (col, relu value v) of `row` into slot s of the adjacency lists
__device__ __forceinline__ void emit(int row, int b, int s, int col, float v) {
    g_list[(size_t)row * LSTRIDE + s] =
        ((unsigned long long)col << 32) | (unsigned long long)__float_as_uint(v);
    int jrow = b * NN + col;
    uint32_t t = atomicAdd((unsigned int*)&g_tcnt[jrow], 1u);
    if (t < TCAP)
        g_list[(size_t)jrow * LSTRIDE + KK + t] =
            ((unsigned long long)(row & 2047) << 32)
          | (unsigned long long)__float_as_uint(v);
}

// ---------------------------------------------------------------------------
// FAST kernel: one block (256 threads) per row. Streams ONLY A (coalesced
// float4); register pre-filter a > 2.2-1.1e-4 (superset of {doped > 2.2})
// pushed straight to smem — the A registers die here, keeping regs ~30.
// Short scattered phase loads noise for the ~29 candidates, certifies
// (#{doped>2.2} >= K ==> global top-K lies in the candidate set), then exact
// rank-count with jax's lowest-index tie-break (key = doped<<11 | 2047-col),
// slot = rank. ANY failure -> append row to retry list and return.
__global__ __launch_bounds__(256) void k_topk(const float* __restrict__ A,
                                              const float* __restrict__ Noise) {
    const int row  = blockIdx.x;       // b * NN + i
    const int tid  = threadIdx.x;
    const int b    = row >> 11;
    const size_t base = (size_t)row << 11;

    __shared__ unsigned long long sP[CAP];   // (a_bits << 11) | col
    __shared__ unsigned long long sK[CAP];   // (doped_bits << 11) | (2047-col)
    __shared__ float    sV[CAP];             // relu value (= a, since a > 0)
    __shared__ uint32_t s_cnt, s_cert;

    if (tid == 0) { s_cnt = 0; s_cert = 0; }
    __syncthreads();

    // ---- stream A, pre-filter in registers, push survivors to smem ----
    {
        const float4* a4 = (const float4*)(A + base);
        float4 av  = __ldcs(a4 + tid);
        float4 av2 = __ldcs(a4 + 256 + tid);
        float aa[8] = {av.x, av.y, av.z, av.w, av2.x, av2.y, av2.z, av2.w};
#pragma unroll
        for (int e = 0; e < 8; e++) {
            if (aa[e] > PREF1) {
                int col = (e < 4) ? (tid * 4 + e) : (1024 + tid * 4 + (e - 4));
                uint32_t p = atomicAdd(&s_cnt, 1u);
                if (p < CAP)
                    sP[p] = ((unsigned long long)__float_as_uint(aa[e]) << 11)
                          | (unsigned long long)col;
            }
        }
    }   // aa[] dead here
    __syncthreads();
    const uint32_t M = s_cnt;

    bool ok = (M >= KK && M <= CAP);
    if (ok) {
        // ---- scattered noise for candidates only; build keys; certify ----
        const uint32_t THB = __float_as_uint(TH1);
        for (uint32_t i = tid; i < M; i += 256) {
            unsigned long long e = sP[i];
            int   col = (int)(e & 2047u);
            float a   = __uint_as_float((uint32_t)(e >> 11));
            float n   = __ldg(Noise + base + col);
            float d   = __fadd_rn(a, __fmul_rn(n, 1e-4f));
            uint32_t dbits = __float_as_uint(d);
            sK[i] = ((unsigned long long)dbits << 11)
                  | (unsigned long long)(2047 - col);
            sV[i] = a;
            if (dbits > THB) atomicAdd(&s_cert, 1u);
        }
        __syncthreads();
        ok = (s_cert >= KK);
    }

    if (!ok) {
        if (tid == 0) {
            int p = atomicAdd(&g_retry_cnt, 1);
            g_retry[p] = row;
        }
        return;
    }

    // ---- exact rank-count within certified superset; slot = rank ----
    for (uint32_t i = tid; i < M; i += 256) {
        const unsigned long long key = sK[i];
        uint32_t rank = 0;
#pragma unroll 4
        for (uint32_t q = 0; q < M; q++)
            rank += (sK[q] > key);
        if (rank < KK)
            emit(row, b, (int)rank, 2047 - (int)(key & 2047u), sV[i]);
    }
}

// ---------------------------------------------------------------------------
// SLOW exact kernel for retried rows (~5%). grid = ROWS; blocks beyond the
// retry count exit immediately. Full coalesced A+noise reload, all 2048 keys
// in registers, 1.8-threshold tier then accept-all; exact rank-count.
__global__ __launch_bounds__(256) void k_retry(const float* __restrict__ A,
                                               const float* __restrict__ Noise) {
    if (blockIdx.x >= (unsigned)g_retry_cnt) return;
    const int row = g_retry[blockIdx.x];
    const int tid = threadIdx.x;
    const int b   = row >> 11;
    const size_t base = (size_t)row << 11;

    __shared__ unsigned long long sK[NN];
    __shared__ float    sV[NN];
    __shared__ uint32_t s_cnt;
    if (tid == 0) s_cnt = 0;

    const float4* a4 = (const float4*)(A + base);
    const float4* n4 = (const float4*)(Noise + base);
    float4 av  = __ldg(a4 + tid);
    float4 av2 = __ldg(a4 + 256 + tid);
    float4 nv  = __ldg(n4 + tid);
    float4 nv2 = __ldg(n4 + 256 + tid);

    float    rv[8];
    uint32_t db[8];
    {
        float aa[8] = {av.x, av.y, av.z, av.w, av2.x, av2.y, av2.z, av2.w};
        float no[8] = {nv.x, nv.y, nv.z, nv.w, nv2.x, nv2.y, nv2.z, nv2.w};
#pragma unroll
        for (int e = 0; e < 8; e++) {
            rv[e] = fmaxf(aa[e], 0.0f);
            float d = __fadd_rn(rv[e], __fmul_rn(no[e], 1e-4f));
            db[e] = __float_as_uint(d);
        }
    }
    __syncthreads();

    // tier @1.8 (register test, no extra loads)
    {
        const uint32_t TH = __float_as_uint(TH2);
#pragma unroll
        for (int e = 0; e < 8; e++) {
            if (db[e] > TH) {
                int col = (e < 4) ? (tid * 4 + e) : (1024 + tid * 4 + (e - 4));
                uint32_t p = atomicAdd(&s_cnt, 1u);
                sK[p] = ((unsigned long long)db[e] << 11)
                      | (unsigned long long)(2047 - col);
                sV[p] = rv[e];
            }
        }
    }
    __syncthreads();
    uint32_t M = s_cnt;

    if (M < KK) {
        // accept-all: exact over all 2048 keys
#pragma unroll
        for (int e = 0; e < 8; e++) {
            int col = (e < 4) ? (tid * 4 + e) : (1024 + tid * 4 + (e - 4));
            sK[col] = ((unsigned long long)db[e] << 11)
                    | (unsigned long long)(2047 - col);
            sV[col] = rv[e];
        }
        __syncthreads();
        M = NN;
    }

    for (uint32_t i = tid; i < M; i += 256) {
        const unsigned long long key = sK[i];
        uint32_t rank = 0;
#pragma unroll 4
        for (uint32_t q = 0; q < M; q++)
            rank += (sK[q] > key);
        if (rank < KK)
            emit(row, b, (int)rank, 2047 - (int)(key & 2047u), sV[i]);
    }
}

// ---------------------------------------------------------------------------
// Warp per row: d_i = 1 + 0.5 * sum(list values); dinv = rsqrt(d_i).
__global__ __launch_bounds__(256) void k_deg() {
    int warp = (blockIdx.x * 256 + threadIdx.x) >> 5;
    int lane = threadIdx.x & 31;
    if (warp >= ROWS) return;
    int tc = g_tcnt[warp]; if (tc > TCAP) tc = TCAP;
    int n  = KK + tc;
    float s = 0.0f;
    const unsigned long long* lst = g_list + (size_t)warp * LSTRIDE;
    for (int i = lane; i < n; i += 32)
        s += __uint_as_float((uint32_t)lst[i]);
#pragma unroll
    for (int off = 16; off; off >>= 1)
        s += __shfl_down_sync(0xffffffffu, s, off);
    if (lane == 0)
        g_dinv[warp] = rsqrtf(fmaf(0.5f, s, 1.0f));
}

// ---------------------------------------------------------------------------
// Block per row: zero smem row, scatter weighted entries + diagonal (dinv via
// L2-hot __ldg), stream dense row out evict-first; re-zero counters.
__global__ __launch_bounds__(256) void k_writer(float* __restrict__ out) {
    const int row = blockIdx.x;
    const int tid = threadIdx.x;
    const int b   = row >> 11;

    __shared__ float srow[NN];
    float4* s4 = (float4*)srow;
    s4[tid]       = make_float4(0.f, 0.f, 0.f, 0.f);
    s4[256 + tid] = make_float4(0.f, 0.f, 0.f, 0.f);

    const float di = g_dinv[row];
    int tc = g_tcnt[row]; if (tc > TCAP) tc = TCAP;
    const int n = KK + tc;
    __syncthreads();

    const unsigned long long* lst = g_list + (size_t)row * LSTRIDE;
    for (int t = tid; t < n; t += 256) {
        unsigned long long e = lst[t];
        int   col = (int)(e >> 32);
        float v   = __uint_as_float((uint32_t)e);
        float w   = 0.5f * v * di * __ldg(&g_dinv[b * NN + col]);
        atomicAdd(&srow[col], w);
    }
    if (tid == 0) atomicAdd(&srow[row & 2047], di * di);
    __syncthreads();

    float4* o4 = (float4*)(out + ((size_t)row << 11));
    __stcs(&o4[tid],       s4[tid]);
    __stcs(&o4[256 + tid], s4[256 + tid]);

    if (tid == 0) g_tcnt[row] = 0;            // next call sees zeroed counters
    if (row == 0 && tid == 1) g_retry_cnt = 0;
}

// ---------------------------------------------------------------------------
extern "C" void kernel_launch(void* const* d_in, const int* in_sizes, int n_in,
                              void* d_out, int out_size) {
    const float* A     = (const float*)d_in[0];
    const float* Noise = (const float*)d_in[1];
    float* out = (float*)d_out;

    k_topk <<<ROWS, 256>>>(A, Noise);
    k_retry<<<ROWS, 256>>>(A, Noise);
    k_deg  <<<(ROWS * 32 + 255) / 256, 256>>>();
    k_writer<<<ROWS, 256>>>(out);
}